// round 14
// baseline (speedup 1.0000x reference)
#include <cuda_runtime.h>
#include <cuda_fp16.h>
#include <cstdint>
#include <math.h>

#define BATCH  4
#define SEQ    2048
#define DIM    512
#define HEADS  8
#define DHEAD  64
#define INNER  512
#define TRIPLE 1536
#define ROWS   (BATCH * SEQ)

typedef uint32_t u32;

// ----------------------------- device scratch ------------------------------
__device__ half g_x  [ROWS * DIM];                          // LN out fp16
__device__ half g_wq [TRIPLE * DIM];                        // w_qkv^T fp16 [N][K]
__device__ half g_wo [INNER * DIM];                         // w_out^T fp16
__device__ half g_q  [BATCH*HEADS*SEQ*DHEAD];               // [b,h,n,dh]
__device__ half g_k  [BATCH*HEADS*SEQ*DHEAD];               // [b,h,n,dh]
__device__ half g_v  [BATCH*HEADS*SEQ*DHEAD];               // [b,h,n,dh]
__device__ half g_ao [ROWS * INNER];                        // attn out fp16

// ----------------------------- helpers ---------------------------------
__device__ __forceinline__ u32 smem_u32(const void* p) {
    u32 a;
    asm("{ .reg .u64 t; cvta.to.shared.u64 t, %1; cvt.u32.u64 %0, t; }" : "=r"(a) : "l"(p));
    return a;
}
__device__ __forceinline__ void ldsm4(u32& r0, u32& r1, u32& r2, u32& r3, u32 addr) {
    asm volatile("ldmatrix.sync.aligned.m8n8.x4.shared.b16 {%0,%1,%2,%3}, [%4];"
        : "=r"(r0), "=r"(r1), "=r"(r2), "=r"(r3) : "r"(addr));
}
__device__ __forceinline__ void ldsm4t(u32& r0, u32& r1, u32& r2, u32& r3, u32 addr) {
    asm volatile("ldmatrix.sync.aligned.m8n8.x4.trans.shared.b16 {%0,%1,%2,%3}, [%4];"
        : "=r"(r0), "=r"(r1), "=r"(r2), "=r"(r3) : "r"(addr));
}
__device__ __forceinline__ void mma16816(float* c, u32 a0, u32 a1, u32 a2, u32 a3,
                                          u32 b0, u32 b1) {
    asm volatile("mma.sync.aligned.m16n8k16.row.col.f32.f16.f16.f32 "
        "{%0,%1,%2,%3}, {%4,%5,%6,%7}, {%8,%9}, {%0,%1,%2,%3};"
        : "+f"(c[0]), "+f"(c[1]), "+f"(c[2]), "+f"(c[3])
        : "r"(a0), "r"(a1), "r"(a2), "r"(a3), "r"(b0), "r"(b1));
}
__device__ __forceinline__ void cpa16(u32 dst, const void* src) {
    asm volatile("cp.async.cg.shared.global [%0], [%1], 16;" :: "r"(dst), "l"(src));
}
#define CP_COMMIT() asm volatile("cp.async.commit_group;" ::: "memory")
#define CP_WAIT(n)  asm volatile("cp.async.wait_group %0;" :: "n"(n) : "memory")

__device__ __forceinline__ u32 pack2h(float x, float y) {
    __half2 h2 = __floats2half2_rn(x, y);
    return *reinterpret_cast<u32*>(&h2);
}

// ---------------------------------------------------------------- LayerNorm
__global__ __launch_bounds__(128)
void ln_kernel(const float* __restrict__ x,
               const float* __restrict__ gamma,
               const float* __restrict__ beta) {
    const int row = blockIdx.x;
    const int t   = threadIdx.x;
    float4 v = ((const float4*)(x + (size_t)row * DIM))[t];
    float s  = v.x + v.y + v.z + v.w;
    float ss = v.x*v.x + v.y*v.y + v.z*v.z + v.w*v.w;
    #pragma unroll
    for (int o = 16; o > 0; o >>= 1) {
        s  += __shfl_xor_sync(0xffffffffu, s,  o);
        ss += __shfl_xor_sync(0xffffffffu, ss, o);
    }
    __shared__ float sh_s[4], sh_ss[4];
    const int w = t >> 5;
    if ((t & 31) == 0) { sh_s[w] = s; sh_ss[w] = ss; }
    __syncthreads();
    s  = sh_s[0] + sh_s[1] + sh_s[2] + sh_s[3];
    ss = sh_ss[0] + sh_ss[1] + sh_ss[2] + sh_ss[3];
    const float mu  = s * (1.0f / DIM);
    const float var = ss * (1.0f / DIM) - mu * mu;
    const float inv = rsqrtf(var + 1e-5f);
    float4 g  = ((const float4*)gamma)[t];
    float4 be = ((const float4*)beta)[t];
    float o0 = (v.x - mu) * inv * g.x + be.x;
    float o1 = (v.y - mu) * inv * g.y + be.y;
    float o2 = (v.z - mu) * inv * g.z + be.z;
    float o3 = (v.w - mu) * inv * g.w + be.w;
    u32* ph = (u32*)(g_x + (size_t)row * DIM);
    ph[t * 2]     = pack2h(o0, o1);
    ph[t * 2 + 1] = pack2h(o2, o3);
}

// ------------------------------------------- weight transpose -> fp16
template<int WHICH>
__global__ __launch_bounds__(256)
void wprep_kernel(const float* __restrict__ w) {
    const int N = WHICH ? INNER : TRIPLE;
    half* th = WHICH ? g_wo : g_wq;
    __shared__ float t[32][33];
    const int bx = blockIdx.x * 32;   // n
    const int by = blockIdx.y * 32;   // k
    const int x = threadIdx.x, y = threadIdx.y;
    #pragma unroll
    for (int i = 0; i < 32; i += 8)
        t[y + i][x] = w[(size_t)(by + y + i) * N + bx + x];
    __syncthreads();
    #pragma unroll
    for (int i = 0; i < 32; i += 8)
        th[(size_t)(bx + y + i) * DIM + by + x] = __float2half(t[x][y + i]);
}

// ------------------------------------------- HMMA fp16 GEMM (cp.async)
// C[8192, NOUT] = A[8192,512] @ B[512,NOUT]; tile 128m x 64n, BK=32, 3 stages.
// 128 threads / 4 warps; warp = 32m x 64n. Stage (12288 B): A@0 (8K), B@8192 (4K).
template<int NOUT, int MODE>
__global__ __launch_bounds__(128, 4)
void hmma_gemm(float* __restrict__ C) {
    __shared__ __align__(128) char sm[36864];   // 3 stages x 12288
    const u32 sb = smem_u32(sm);
    const int tid = threadIdx.x, w = tid >> 5, lane = tid & 31;
    const int bm = blockIdx.y * 128, bn = blockIdx.x * 64;

    const half* A = MODE ? g_ao : g_x;
    const half* B = MODE ? g_wo : g_wq;

    u32 dA[4]; u32 offA[4];
    #pragma unroll
    for (int i = 0; i < 4; ++i) {
        const int c = tid + i * 128, l = c >> 3, s = c & 7;
        dA[i] = l * 128 + ((s * 16) ^ ((l & 7) << 4));
        offA[i] = (u32)((bm + l * 2 + (s >> 2)) * DIM + (s & 3) * 8);
    }
    u32 dB[2]; u32 offB[2];
    #pragma unroll
    for (int i = 0; i < 2; ++i) {
        const int c = tid + i * 128, l = c >> 3, s = c & 7;
        dB[i] = l * 128 + ((s * 16) ^ ((l & 7) << 4));
        offB[i] = (u32)((bn + l * 2 + (s >> 2)) * DIM + (s & 3) * 8);
    }

    const int ar0 = w * 32 + (lane & 15), ar1 = ar0 + 16;
    u32 aaddr0[2], aaddr1[2];
    #pragma unroll
    for (int ks = 0; ks < 2; ++ks) {
        const u32 kb = (u32)(lane & 16) + ks * 32;
        aaddr0[ks] = (ar0 >> 1) * 128 + ((((ar0 & 1) * 64) + kb) ^ (((ar0 >> 1) & 7) << 4));
        aaddr1[ks] = (ar1 >> 1) * 128 + ((((ar1 & 1) * 64) + kb) ^ (((ar1 >> 1) & 7) << 4));
    }
    const int brow = (lane & 7) + ((lane & 16) >> 1);
    u32 baddr[4][2];
    #pragma unroll
    for (int p = 0; p < 4; ++p) {
        const int r = p * 16 + brow;
        #pragma unroll
        for (int ks = 0; ks < 2; ++ks) {
            const u32 kb = (u32)((lane & 8) << 1) + ks * 32;
            baddr[p][ks] = (r >> 1) * 128 + ((((r & 1) * 64) + kb) ^ (((r >> 1) & 7) << 4));
        }
    }

    float acc[16][4];
    #pragma unroll
    for (int j = 0; j < 16; ++j)
        #pragma unroll
        for (int i = 0; i < 4; ++i) acc[j][i] = 0.f;

    #pragma unroll
    for (int s = 0; s < 2; ++s) {
        const u32 base = sb + s * 12288;
        const u32 ko = (u32)s * 32;
        #pragma unroll
        for (int i = 0; i < 4; ++i) cpa16(base + dA[i], A + offA[i] + ko);
        #pragma unroll
        for (int i = 0; i < 2; ++i) cpa16(base + 8192 + dB[i], B + offB[i] + ko);
        CP_COMMIT();
    }

    for (int kt = 0; kt < 16; ++kt) {
        CP_WAIT(1);
        __syncthreads();
        if (kt + 2 < 16) {
            const u32 base = sb + ((kt + 2) % 3) * 12288;
            const u32 ko = (u32)(kt + 2) * 32;
            #pragma unroll
            for (int i = 0; i < 4; ++i) cpa16(base + dA[i], A + offA[i] + ko);
            #pragma unroll
            for (int i = 0; i < 2; ++i) cpa16(base + 8192 + dB[i], B + offB[i] + ko);
            CP_COMMIT();
        }
        const u32 base = sb + (kt % 3) * 12288;
        const u32 bb = base + 8192;
        #pragma unroll
        for (int ks = 0; ks < 2; ++ks) {
            u32 a0, a1, a2, a3, a4, a5, a6, a7;
            ldsm4(a0, a1, a2, a3, base + aaddr0[ks]);
            ldsm4(a4, a5, a6, a7, base + aaddr1[ks]);
            #pragma unroll
            for (int p = 0; p < 4; ++p) {
                u32 r0, r1, r2, r3;
                ldsm4(r0, r1, r2, r3, bb + baddr[p][ks]);
                mma16816(acc[2 * p],         a0, a1, a2, a3, r0, r1);
                mma16816(acc[2 * p + 1],     a0, a1, a2, a3, r2, r3);
                mma16816(acc[8 + 2 * p],     a4, a5, a6, a7, r0, r1);
                mma16816(acc[8 + 2 * p + 1], a4, a5, a6, a7, r2, r3);
            }
        }
    }

    const int q  = lane >> 2;
    const int qq = (lane & 3) * 2;
    #pragma unroll
    for (int half_ = 0; half_ < 2; ++half_) {
        const int r0 = bm + w * 32 + half_ * 16 + q;
        float (*af)[4] = &acc[half_ * 8];
        if (MODE == 1) {
            #pragma unroll
            for (int ja = 0; ja < 8; ++ja) {
                const int col = bn + ja * 8 + qq;
                *(float2*)(C + (size_t)r0 * NOUT + col)       = make_float2(af[ja][0], af[ja][1]);
                *(float2*)(C + (size_t)(r0 + 8) * NOUT + col) = make_float2(af[ja][2], af[ja][3]);
            }
        } else {
            const int part = bn >> 9;
            half* dst = (part == 0) ? g_q : (part == 1 ? g_k : g_v);
            const int h  = (bn & 511) >> 6;
            const int bb = r0 >> 11, nn = r0 & 2047;
            const size_t hb = ((size_t)(bb * HEADS + h) * SEQ + nn) * DHEAD;
            #pragma unroll
            for (int ja = 0; ja < 8; ++ja) {
                const int d = ja * 8 + qq;
                *(u32*)(dst + hb + d)             = pack2h(af[ja][0], af[ja][1]);
                *(u32*)(dst + hb + 8 * DHEAD + d) = pack2h(af[ja][2], af[ja][3]);
            }
        }
    }
}

// ------------------------------------------- HMMA fp16 attention (cp.async)
// Block: 256 thr (8 warps), 128 queries of one (b,h); 32-key tiles, 2-stage ring.
// SMEM: Q@0 (16K); stage s @16384+s*8192: K (4K) + V (4K). 32K total.
// Per-warp footprint identical to R13 (16 q-rows) -> same arithmetic order.
__global__ __launch_bounds__(256)
void hmma_attn(const float* __restrict__ pose, const float* __restrict__ beta_p) {
    __shared__ __align__(128) char sm[32768];
    const u32 sb = smem_u32(sm);
    const int tid = threadIdx.x, w = tid >> 5, lane = tid & 31;
    const int q0 = blockIdx.x * 128, bh = blockIdx.y, b = bh >> 3, h = bh & 7;

    const half* kp = g_k + (size_t)bh * SEQ * DHEAD;
    const half* vp = g_v + (size_t)bh * SEQ * DHEAD;

    {
        const half* qp = g_q + ((size_t)bh * SEQ + q0) * DHEAD;
        #pragma unroll
        for (int i = 0; i < 4; ++i) {
            const int c = tid + i * 256, r = c >> 3, s = c & 7;
            const u32 d = r * 128 + ((s * 16) ^ ((r & 7) << 4));
            cpa16(sb + d, qp + (size_t)r * DHEAD + s * 8);
        }
        {   // first K/V stage: 256 K-chunks + 256 V-chunks, one each
            const int c = tid, r = c >> 3, s = c & 7;
            const u32 d = r * 128 + ((s * 16) ^ ((r & 7) << 4));
            const size_t off = (size_t)r * DHEAD + s * 8;
            cpa16(sb + 16384 +        d, kp + off);
            cpa16(sb + 16384 + 4096 + d, vp + off);
        }
        CP_COMMIT();
    }

    const float bet = *beta_p;
    const int q  = lane >> 2;
    const int qq = (lane & 3) * 2;
    const float bq0 = bet * __ldg(&pose[(size_t)b * SEQ + q0 + w * 16 + q]);
    const float bq1 = bet * __ldg(&pose[(size_t)b * SEQ + q0 + w * 16 + q + 8]);
    const float* pb = pose + (size_t)b * SEQ;

    const u32 swz  = (u32)((lane & 7) << 4);
    const u32 aoff = (u32)((w * 16 + (lane & 15)) * 128);
    const u32 acb  = (u32)(lane & 16);
    const int brow = (lane & 7) + ((lane & 16) >> 1);
    const u32 bcb  = (u32)((lane & 8) << 1);
    const int vrow = (lane & 7) + (lane & 8);
    const u32 vcb  = (u32)(lane & 16);

    float o[8][4];
    #pragma unroll
    for (int j = 0; j < 8; ++j)
        #pragma unroll
        for (int i = 0; i < 4; ++i) o[j][i] = 0.f;
    float ls0 = 0.f, ls1 = 0.f;

    for (int t = 0; t < 64; ++t) {
        const int j0 = t * 32;
        CP_WAIT(0);
        __syncthreads();
        if (t + 1 < 64) {
            const u32 base = sb + 16384 + ((t + 1) & 1) * 8192;
            const int c = tid, r = c >> 3, s = c & 7;
            const u32 d = r * 128 + ((s * 16) ^ ((r & 7) << 4));
            const size_t off = (size_t)(j0 + 32 + r) * DHEAD + s * 8;
            cpa16(base +        d, kp + off);
            cpa16(base + 4096 + d, vp + off);
            CP_COMMIT();
        }
        const u32 kb_ = sb + 16384 + (t & 1) * 8192;
        const u32 vb_ = kb_ + 4096;

        // ---- S = Q @ K^T  (1 pass)
        float s[4][4];
        #pragma unroll
        for (int j = 0; j < 4; ++j)
            #pragma unroll
            for (int i = 0; i < 4; ++i) s[j][i] = 0.f;
        #pragma unroll
        for (int ks = 0; ks < 4; ++ks) {
            const u32 kc = (u32)(ks * 32);
            u32 a0, a1, a2, a3;
            ldsm4(a0, a1, a2, a3, sb + aoff + ((kc + acb) ^ swz));
            #pragma unroll
            for (int p = 0; p < 2; ++p) {
                u32 r0, r1, r2, r3;
                ldsm4(r0, r1, r2, r3, kb_ + (u32)((p * 16 + brow) * 128) + ((kc + bcb) ^ swz));
                mma16816(s[2 * p],     a0, a1, a2, a3, r0, r1);
                mma16816(s[2 * p + 1], a0, a1, a2, a3, r2, r3);
            }
        }

        // ---- softmax (unnormalized), fp16 P fragments (row sums exact fp32)
        u32 Ph[2][4];
        #pragma unroll
        for (int ja = 0; ja < 4; ++ja) {
            const int col = ja * 8 + qq;
            const float bk0 = bet * __ldg(&pb[j0 + col]);
            const float bk1 = bet * __ldg(&pb[j0 + col + 1]);
            float e0 = __expf(fmaf(s[ja][0], 0.125f, bq0 + bk0));
            float e1 = __expf(fmaf(s[ja][1], 0.125f, bq0 + bk1));
            float e2 = __expf(fmaf(s[ja][2], 0.125f, bq1 + bk0));
            float e3 = __expf(fmaf(s[ja][3], 0.125f, bq1 + bk1));
            ls0 += e0 + e1;
            ls1 += e2 + e3;
            const int ka = ja >> 1, base = (ja & 1) * 2;
            Ph[ka][base]     = pack2h(e0, e1);
            Ph[ka][base + 1] = pack2h(e2, e3);
        }

        // ---- O += P @ V  (1 pass)
        #pragma unroll
        for (int ks = 0; ks < 2; ++ks) {
            const u32* A = Ph[ks];
            const u32 rbase = vb_ + (u32)((ks * 16 + vrow) * 128);
            #pragma unroll
            for (int p = 0; p < 4; ++p) {
                u32 r0, r1, r2, r3;
                ldsm4t(r0, r1, r2, r3, rbase + ((u32)(p * 32 + vcb) ^ swz));
                mma16816(o[2 * p],     A[0], A[1], A[2], A[3], r0, r1);
                mma16816(o[2 * p + 1], A[0], A[1], A[2], A[3], r2, r3);
            }
        }
    }

    ls0 += __shfl_xor_sync(0xffffffffu, ls0, 1);
    ls0 += __shfl_xor_sync(0xffffffffu, ls0, 2);
    ls1 += __shfl_xor_sync(0xffffffffu, ls1, 1);
    ls1 += __shfl_xor_sync(0xffffffffu, ls1, 2);
    const float inv0 = 1.0f / ls0, inv1 = 1.0f / ls1;

    const int r0 = q0 + w * 16 + q;
    #pragma unroll
    for (int ja = 0; ja < 8; ++ja) {
        const int col = h * DHEAD + ja * 8 + qq;
        *(u32*)(g_ao + ((size_t)(b * SEQ + r0))     * INNER + col) =
            pack2h(o[ja][0] * inv0, o[ja][1] * inv0);
        *(u32*)(g_ao + ((size_t)(b * SEQ + r0 + 8)) * INNER + col) =
            pack2h(o[ja][2] * inv1, o[ja][3] * inv1);
    }
}

// --------------------------------------------------------------- launcher
extern "C" void kernel_launch(void* const* d_in, const int* in_sizes, int n_in,
                              void* d_out, int out_size) {
    const float* x         = (const float*)d_in[0];
    const float* pose_bias = (const float*)d_in[1];
    const float* ln_gamma  = (const float*)d_in[2];
    const float* ln_beta   = (const float*)d_in[3];
    const float* w_qkv     = (const float*)d_in[4];
    const float* w_out     = (const float*)d_in[5];
    const float* beta      = (const float*)d_in[6];
    float* out = (float*)d_out;

    ln_kernel<<<ROWS, 128>>>(x, ln_gamma, ln_beta);
    wprep_kernel<0><<<dim3(TRIPLE / 32, DIM / 32), dim3(32, 8)>>>(w_qkv);
    wprep_kernel<1><<<dim3(INNER / 32, DIM / 32), dim3(32, 8)>>>(w_out);
    hmma_gemm<TRIPLE, 0><<<dim3(TRIPLE / 64, ROWS / 128), 128>>>(nullptr);
    hmma_attn<<<dim3(SEQ / 128, BATCH * HEADS), 256>>>(pose_bias, beta);
    hmma_gemm<INNER, 1><<<dim3(INNER / 64, ROWS / 128), 128>>>(out);
}

// round 16
// speedup vs baseline: 1.1374x; 1.1374x over previous
#include <cuda_runtime.h>
#include <cuda_fp16.h>
#include <cstdint>
#include <math.h>

#define BATCH  4
#define SEQ    2048
#define DIM    512
#define HEADS  8
#define DHEAD  64
#define INNER  512
#define TRIPLE 1536
#define ROWS   (BATCH * SEQ)

typedef uint32_t u32;

// ----------------------------- device scratch ------------------------------
__device__ half g_x  [ROWS * DIM];
__device__ half g_wq [TRIPLE * DIM];
__device__ half g_wo [INNER * DIM];
__device__ half g_q  [BATCH*HEADS*SEQ*DHEAD];
__device__ half g_k  [BATCH*HEADS*SEQ*DHEAD];
__device__ half g_v  [BATCH*HEADS*SEQ*DHEAD];
__device__ half g_ao [ROWS * INNER];

// ----------------------------- helpers ---------------------------------
__device__ __forceinline__ u32 smem_u32(const void* p) {
    u32 a;
    asm("{ .reg .u64 t; cvta.to.shared.u64 t, %1; cvt.u32.u64 %0, t; }" : "=r"(a) : "l"(p));
    return a;
}
__device__ __forceinline__ void ldsm4(u32& r0, u32& r1, u32& r2, u32& r3, u32 addr) {
    asm volatile("ldmatrix.sync.aligned.m8n8.x4.shared.b16 {%0,%1,%2,%3}, [%4];"
        : "=r"(r0), "=r"(r1), "=r"(r2), "=r"(r3) : "r"(addr));
}
__device__ __forceinline__ void ldsm4t(u32& r0, u32& r1, u32& r2, u32& r3, u32 addr) {
    asm volatile("ldmatrix.sync.aligned.m8n8.x4.trans.shared.b16 {%0,%1,%2,%3}, [%4];"
        : "=r"(r0), "=r"(r1), "=r"(r2), "=r"(r3) : "r"(addr));
}
__device__ __forceinline__ void mma16816(float* c, u32 a0, u32 a1, u32 a2, u32 a3,
                                          u32 b0, u32 b1) {
    asm volatile("mma.sync.aligned.m16n8k16.row.col.f32.f16.f16.f32 "
        "{%0,%1,%2,%3}, {%4,%5,%6,%7}, {%8,%9}, {%0,%1,%2,%3};"
        : "+f"(c[0]), "+f"(c[1]), "+f"(c[2]), "+f"(c[3])
        : "r"(a0), "r"(a1), "r"(a2), "r"(a3), "r"(b0), "r"(b1));
}
__device__ __forceinline__ void cpa16(u32 dst, const void* src) {
    asm volatile("cp.async.cg.shared.global [%0], [%1], 16;" :: "r"(dst), "l"(src));
}
#define CP_COMMIT() asm volatile("cp.async.commit_group;" ::: "memory")
#define CP_WAIT(n)  asm volatile("cp.async.wait_group %0;" :: "n"(n) : "memory")

__device__ __forceinline__ u32 pack2h(float x, float y) {
    __half2 h2 = __floats2half2_rn(x, y);
    return *reinterpret_cast<u32*>(&h2);
}

// ---------------------------------------------------------------- LayerNorm
__global__ __launch_bounds__(128)
void ln_kernel(const float* __restrict__ x,
               const float* __restrict__ gamma,
               const float* __restrict__ beta) {
    const int row = blockIdx.x;
    const int t   = threadIdx.x;
    float4 v = ((const float4*)(x + (size_t)row * DIM))[t];
    float s  = v.x + v.y + v.z + v.w;
    float ss = v.x*v.x + v.y*v.y + v.z*v.z + v.w*v.w;
    #pragma unroll
    for (int o = 16; o > 0; o >>= 1) {
        s  += __shfl_xor_sync(0xffffffffu, s,  o);
        ss += __shfl_xor_sync(0xffffffffu, ss, o);
    }
    __shared__ float sh_s[4], sh_ss[4];
    const int w = t >> 5;
    if ((t & 31) == 0) { sh_s[w] = s; sh_ss[w] = ss; }
    __syncthreads();
    s  = sh_s[0] + sh_s[1] + sh_s[2] + sh_s[3];
    ss = sh_ss[0] + sh_ss[1] + sh_ss[2] + sh_ss[3];
    const float mu  = s * (1.0f / DIM);
    const float var = ss * (1.0f / DIM) - mu * mu;
    const float inv = rsqrtf(var + 1e-5f);
    float4 g  = ((const float4*)gamma)[t];
    float4 be = ((const float4*)beta)[t];
    float o0 = (v.x - mu) * inv * g.x + be.x;
    float o1 = (v.y - mu) * inv * g.y + be.y;
    float o2 = (v.z - mu) * inv * g.z + be.z;
    float o3 = (v.w - mu) * inv * g.w + be.w;
    u32* ph = (u32*)(g_x + (size_t)row * DIM);
    ph[t * 2]     = pack2h(o0, o1);
    ph[t * 2 + 1] = pack2h(o2, o3);
}

// ------------------------------------------- weight transpose -> fp16 (merged)
// grid.x: blocks [0,48) -> w_qkv (N=1536), blocks [48,64) -> w_out (N=512)
__global__ __launch_bounds__(256)
void wprep_kernel(const float* __restrict__ wq, const float* __restrict__ wo) {
    const bool second = blockIdx.x >= (TRIPLE / 32);
    const float* w = second ? wo : wq;
    const int N    = second ? INNER : TRIPLE;
    half* th       = second ? g_wo : g_wq;
    const int bx = (second ? blockIdx.x - TRIPLE / 32 : blockIdx.x) * 32;
    const int by = blockIdx.y * 32;
    __shared__ float t[32][33];
    const int x = threadIdx.x, y = threadIdx.y;
    #pragma unroll
    for (int i = 0; i < 32; i += 8)
        t[y + i][x] = w[(size_t)(by + y + i) * N + bx + x];
    __syncthreads();
    #pragma unroll
    for (int i = 0; i < 32; i += 8)
        th[(size_t)(bx + y + i) * DIM + by + x] = __float2half(t[x][y + i]);
}

// ------------------------------------------- HMMA fp16 GEMM (cp.async)
// C[8192, NOUT] = A[8192,512] @ B[512,NOUT]; tile 128m x 64n, BK=64, 2 stages.
// 128 threads / 4 warps; warp = 32m x 64n.
// Stage (24576 B): A@0 (16K, 128 rows x 128B), B@16384 (8K, 64 rows x 128B).
// Simple layout: 1 row per 128B line, SW128 XOR per line (same as attention).
// 8 barriers total (was 16); 64 MMAs per warp per chunk.
template<int NOUT, int MODE>
__global__ __launch_bounds__(128, 4)
void hmma_gemm(float* __restrict__ C) {
    __shared__ __align__(128) char sm[49152];   // 2 stages x 24576
    const u32 sb = smem_u32(sm);
    const int tid = threadIdx.x, w = tid >> 5, lane = tid & 31;
    const int bm = blockIdx.y * 128, bn = blockIdx.x * 64;

    const half* A = MODE ? g_ao : g_x;
    const half* B = MODE ? g_wo : g_wq;

    // cp.async: A 8 chunks/thread, B 4 chunks/thread (16B each)
    u32 dA[8]; u32 offA[8];
    #pragma unroll
    for (int i = 0; i < 8; ++i) {
        const int c = tid + i * 128, r = c >> 3, s = c & 7;
        dA[i] = r * 128 + ((s * 16) ^ ((r & 7) << 4));
        offA[i] = (u32)((bm + r) * DIM + s * 8);
    }
    u32 dB[4]; u32 offB[4];
    #pragma unroll
    for (int i = 0; i < 4; ++i) {
        const int c = tid + i * 128, r = c >> 3, s = c & 7;
        dB[i] = r * 128 + ((s * 16) ^ ((r & 7) << 4));
        offB[i] = (u32)((bn + r) * DIM + s * 8);
    }

    // ldsm addresses (1 row per line)
    const int ar0 = w * 32 + (lane & 15), ar1 = ar0 + 16;
    u32 aaddr0[4], aaddr1[4];
    #pragma unroll
    for (int ks = 0; ks < 4; ++ks) {
        const u32 kb = (u32)(lane & 16) + ks * 32;
        aaddr0[ks] = ar0 * 128 + (kb ^ ((ar0 & 7) << 4));
        aaddr1[ks] = ar1 * 128 + (kb ^ ((ar1 & 7) << 4));
    }
    const int brow = (lane & 7) + ((lane & 16) >> 1);
    u32 baddr[4][4];
    #pragma unroll
    for (int p = 0; p < 4; ++p) {
        const int r = p * 16 + brow;
        #pragma unroll
        for (int ks = 0; ks < 4; ++ks) {
            const u32 kb = (u32)((lane & 8) << 1) + ks * 32;
            baddr[p][ks] = r * 128 + (kb ^ ((r & 7) << 4));
        }
    }

    float acc[16][4];
    #pragma unroll
    for (int j = 0; j < 16; ++j)
        #pragma unroll
        for (int i = 0; i < 4; ++i) acc[j][i] = 0.f;

    // prologue: stage 0
    {
        #pragma unroll
        for (int i = 0; i < 8; ++i) cpa16(sb + dA[i], A + offA[i]);
        #pragma unroll
        for (int i = 0; i < 4; ++i) cpa16(sb + 16384 + dB[i], B + offB[i]);
        CP_COMMIT();
    }

    for (int kt = 0; kt < 8; ++kt) {
        CP_WAIT(0);
        __syncthreads();
        if (kt + 1 < 8) {
            const u32 base = sb + ((kt + 1) & 1) * 24576;
            const u32 ko = (u32)(kt + 1) * 64;
            #pragma unroll
            for (int i = 0; i < 8; ++i) cpa16(base + dA[i], A + offA[i] + ko);
            #pragma unroll
            for (int i = 0; i < 4; ++i) cpa16(base + 16384 + dB[i], B + offB[i] + ko);
            CP_COMMIT();
        }
        const u32 base = sb + (kt & 1) * 24576;
        const u32 bb = base + 16384;
        #pragma unroll
        for (int ks = 0; ks < 4; ++ks) {
            u32 a0, a1, a2, a3, a4, a5, a6, a7;
            ldsm4(a0, a1, a2, a3, base + aaddr0[ks]);
            ldsm4(a4, a5, a6, a7, base + aaddr1[ks]);
            #pragma unroll
            for (int p = 0; p < 4; ++p) {
                u32 r0, r1, r2, r3;
                ldsm4(r0, r1, r2, r3, bb + baddr[p][ks]);
                mma16816(acc[2 * p],         a0, a1, a2, a3, r0, r1);
                mma16816(acc[2 * p + 1],     a0, a1, a2, a3, r2, r3);
                mma16816(acc[8 + 2 * p],     a4, a5, a6, a7, r0, r1);
                mma16816(acc[8 + 2 * p + 1], a4, a5, a6, a7, r2, r3);
            }
        }
    }

    const int q  = lane >> 2;
    const int qq = (lane & 3) * 2;
    #pragma unroll
    for (int half_ = 0; half_ < 2; ++half_) {
        const int r0 = bm + w * 32 + half_ * 16 + q;
        float (*af)[4] = &acc[half_ * 8];
        if (MODE == 1) {
            #pragma unroll
            for (int ja = 0; ja < 8; ++ja) {
                const int col = bn + ja * 8 + qq;
                *(float2*)(C + (size_t)r0 * NOUT + col)       = make_float2(af[ja][0], af[ja][1]);
                *(float2*)(C + (size_t)(r0 + 8) * NOUT + col) = make_float2(af[ja][2], af[ja][3]);
            }
        } else {
            const int part = bn >> 9;
            half* dst = (part == 0) ? g_q : (part == 1 ? g_k : g_v);
            const int h  = (bn & 511) >> 6;
            const int bb2 = r0 >> 11, nn = r0 & 2047;
            const size_t hb = ((size_t)(bb2 * HEADS + h) * SEQ + nn) * DHEAD;
            #pragma unroll
            for (int ja = 0; ja < 8; ++ja) {
                const int d = ja * 8 + qq;
                *(u32*)(dst + hb + d)             = pack2h(af[ja][0], af[ja][1]);
                *(u32*)(dst + hb + 8 * DHEAD + d) = pack2h(af[ja][2], af[ja][3]);
            }
        }
    }
}

// ------------------------------------------- HMMA fp16 attention (cp.async)
// [R13-exact: 128 thr / 4 warps, 64 queries, 32-key tiles, 2-stage ring.]
// SMEM: Q@0 (8K); stage s @8192+s*8192: K (4K) + V (4K). 24K total.
__global__ __launch_bounds__(128, 3)
void hmma_attn(const float* __restrict__ pose, const float* __restrict__ beta_p) {
    __shared__ __align__(128) char sm[24576];
    const u32 sb = smem_u32(sm);
    const int tid = threadIdx.x, w = tid >> 5, lane = tid & 31;
    const int q0 = blockIdx.x * 64, bh = blockIdx.y, b = bh >> 3, h = bh & 7;

    const half* kp = g_k + (size_t)bh * SEQ * DHEAD;
    const half* vp = g_v + (size_t)bh * SEQ * DHEAD;

    {
        const half* qp = g_q + ((size_t)bh * SEQ + q0) * DHEAD;
        #pragma unroll
        for (int i = 0; i < 4; ++i) {
            const int c = tid + i * 128, r = c >> 3, s = c & 7;
            const u32 d = r * 128 + ((s * 16) ^ ((r & 7) << 4));
            cpa16(sb + d, qp + (size_t)r * DHEAD + s * 8);
        }
        #pragma unroll
        for (int i = 0; i < 2; ++i) {
            const int c = tid + i * 128, r = c >> 3, s = c & 7;
            const u32 d = r * 128 + ((s * 16) ^ ((r & 7) << 4));
            const size_t off = (size_t)r * DHEAD + s * 8;
            cpa16(sb + 8192 +        d, kp + off);
            cpa16(sb + 8192 + 4096 + d, vp + off);
        }
        CP_COMMIT();
    }

    const float bet = *beta_p;
    const int q  = lane >> 2;
    const int qq = (lane & 3) * 2;
    const float bq0 = bet * __ldg(&pose[(size_t)b * SEQ + q0 + w * 16 + q]);
    const float bq1 = bet * __ldg(&pose[(size_t)b * SEQ + q0 + w * 16 + q + 8]);
    const float* pb = pose + (size_t)b * SEQ;

    const u32 swz  = (u32)((lane & 7) << 4);
    const u32 aoff = (u32)((w * 16 + (lane & 15)) * 128);
    const u32 acb  = (u32)(lane & 16);
    const int brow = (lane & 7) + ((lane & 16) >> 1);
    const u32 bcb  = (u32)((lane & 8) << 1);
    const int vrow = (lane & 7) + (lane & 8);
    const u32 vcb  = (u32)(lane & 16);

    float o[8][4];
    #pragma unroll
    for (int j = 0; j < 8; ++j)
        #pragma unroll
        for (int i = 0; i < 4; ++i) o[j][i] = 0.f;
    float ls0 = 0.f, ls1 = 0.f;

    for (int t = 0; t < 64; ++t) {
        const int j0 = t * 32;
        CP_WAIT(0);
        __syncthreads();
        if (t + 1 < 64) {
            const u32 base = sb + 8192 + ((t + 1) & 1) * 8192;
            #pragma unroll
            for (int i = 0; i < 2; ++i) {
                const int c = tid + i * 128, r = c >> 3, s = c & 7;
                const u32 d = r * 128 + ((s * 16) ^ ((r & 7) << 4));
                const size_t off = (size_t)(j0 + 32 + r) * DHEAD + s * 8;
                cpa16(base +        d, kp + off);
                cpa16(base + 4096 + d, vp + off);
            }
            CP_COMMIT();
        }
        const u32 kb_ = sb + 8192 + (t & 1) * 8192;
        const u32 vb_ = kb_ + 4096;

        float s[4][4];
        #pragma unroll
        for (int j = 0; j < 4; ++j)
            #pragma unroll
            for (int i = 0; i < 4; ++i) s[j][i] = 0.f;
        #pragma unroll
        for (int ks = 0; ks < 4; ++ks) {
            const u32 kc = (u32)(ks * 32);
            u32 a0, a1, a2, a3;
            ldsm4(a0, a1, a2, a3, sb + aoff + ((kc + acb) ^ swz));
            #pragma unroll
            for (int p = 0; p < 2; ++p) {
                u32 r0, r1, r2, r3;
                ldsm4(r0, r1, r2, r3, kb_ + (u32)((p * 16 + brow) * 128) + ((kc + bcb) ^ swz));
                mma16816(s[2 * p],     a0, a1, a2, a3, r0, r1);
                mma16816(s[2 * p + 1], a0, a1, a2, a3, r2, r3);
            }
        }

        u32 Ph[2][4];
        #pragma unroll
        for (int ja = 0; ja < 4; ++ja) {
            const int col = ja * 8 + qq;
            const float bk0 = bet * __ldg(&pb[j0 + col]);
            const float bk1 = bet * __ldg(&pb[j0 + col + 1]);
            float e0 = __expf(fmaf(s[ja][0], 0.125f, bq0 + bk0));
            float e1 = __expf(fmaf(s[ja][1], 0.125f, bq0 + bk1));
            float e2 = __expf(fmaf(s[ja][2], 0.125f, bq1 + bk0));
            float e3 = __expf(fmaf(s[ja][3], 0.125f, bq1 + bk1));
            ls0 += e0 + e1;
            ls1 += e2 + e3;
            const int ka = ja >> 1, base = (ja & 1) * 2;
            Ph[ka][base]     = pack2h(e0, e1);
            Ph[ka][base + 1] = pack2h(e2, e3);
        }

        #pragma unroll
        for (int ks = 0; ks < 2; ++ks) {
            const u32* A = Ph[ks];
            const u32 rbase = vb_ + (u32)((ks * 16 + vrow) * 128);
            #pragma unroll
            for (int p = 0; p < 4; ++p) {
                u32 r0, r1, r2, r3;
                ldsm4t(r0, r1, r2, r3, rbase + ((u32)(p * 32 + vcb) ^ swz));
                mma16816(o[2 * p],     A[0], A[1], A[2], A[3], r0, r1);
                mma16816(o[2 * p + 1], A[0], A[1], A[2], A[3], r2, r3);
            }
        }
    }

    ls0 += __shfl_xor_sync(0xffffffffu, ls0, 1);
    ls0 += __shfl_xor_sync(0xffffffffu, ls0, 2);
    ls1 += __shfl_xor_sync(0xffffffffu, ls1, 1);
    ls1 += __shfl_xor_sync(0xffffffffu, ls1, 2);
    const float inv0 = 1.0f / ls0, inv1 = 1.0f / ls1;

    const int r0 = q0 + w * 16 + q;
    #pragma unroll
    for (int ja = 0; ja < 8; ++ja) {
        const int col = h * DHEAD + ja * 8 + qq;
        *(u32*)(g_ao + ((size_t)(b * SEQ + r0))     * INNER + col) =
            pack2h(o[ja][0] * inv0, o[ja][1] * inv0);
        *(u32*)(g_ao + ((size_t)(b * SEQ + r0 + 8)) * INNER + col) =
            pack2h(o[ja][2] * inv1, o[ja][3] * inv1);
    }
}

// --------------------------------------------------------------- launcher
extern "C" void kernel_launch(void* const* d_in, const int* in_sizes, int n_in,
                              void* d_out, int out_size) {
    const float* x         = (const float*)d_in[0];
    const float* pose_bias = (const float*)d_in[1];
    const float* ln_gamma  = (const float*)d_in[2];
    const float* ln_beta   = (const float*)d_in[3];
    const float* w_qkv     = (const float*)d_in[4];
    const float* w_out     = (const float*)d_in[5];
    const float* beta      = (const float*)d_in[6];
    float* out = (float*)d_out;

    ln_kernel<<<ROWS, 128>>>(x, ln_gamma, ln_beta);
    wprep_kernel<<<dim3(TRIPLE / 32 + INNER / 32, DIM / 32), dim3(32, 8)>>>(w_qkv, w_out);
    hmma_gemm<TRIPLE, 0><<<dim3(TRIPLE / 64, ROWS / 128), 128>>>(nullptr);
    hmma_attn<<<dim3(SEQ / 64, BATCH * HEADS), 128>>>(pose_bias, beta);
    hmma_gemm<INNER, 1><<<dim3(INNER / 64, ROWS / 128), 128>>>(out);
}